// round 16
// baseline (speedup 1.0000x reference)
#include <cuda_runtime.h>
#include <cuda_bf16.h>
#include <cstdint>

// Problem constants (shapes fixed by the dataset; sizes re-derived from in_sizes)
#define MAX_NODES 100000
#define IN_DIM    64
#define HID_DIM   32

// Scratch (allocation-free rule: __device__ globals).
// Device globals are zero-initialized at module load, and k_finalize re-zeros
// both degree arrays after consuming them, so every kernel_launch call
// (correctness run, graph capture, every replay) starts from zeroed counters.
__device__ int   g_deg_out[MAX_NODES];
__device__ int   g_deg_in [MAX_NODES];
__device__ float g_h      [MAX_NODES * HID_DIM];   // (X@W) * norm_src

// ---------------------------------------------------------------------------
// K1: zero the output accumulator (d_out is poisoned) + out-degree histogram.
//     Disjoint arrays -> safe in one kernel. Histogram: 4 edges/unit (int4).
// ---------------------------------------------------------------------------
__global__ void k_zero_hist(float4* __restrict__ out4,
                            const int* __restrict__ src,
                            int n, int E) {
    int tid = blockIdx.x * blockDim.x + threadIdx.x;
    int gstride = gridDim.x * blockDim.x;

    int tot4 = n * (HID_DIM / 4);
    float4 z = make_float4(0.f, 0.f, 0.f, 0.f);
    for (int i = tid; i < tot4; i += gstride)
        out4[i] = z;

    int units = (E + 3) / 4;
    for (int u = tid; u < units; u += gstride) {
        int base = u * 4;
        if (base + 3 < E) {
            int4 s = __ldg(reinterpret_cast<const int4*>(src + base));
            atomicAdd(&g_deg_out[s.x], 1);
            atomicAdd(&g_deg_out[s.y], 1);
            atomicAdd(&g_deg_out[s.z], 1);
            atomicAdd(&g_deg_out[s.w], 1);
        } else {
            for (int i = base; i < E; i++)
                atomicAdd(&g_deg_out[__ldg(src + i)], 1);
        }
    }
}

// ---------------------------------------------------------------------------
// K2: h = (X @ W) * rsqrt(max(deg_out,1)).
//     4 threads per row (q = tid&3 owns cols q*8..q*8+7): grid is 4x larger
//     (1563 blocks vs 391) so occupancy is no longer the FMA-issue ceiling;
//     acc shrinks to 8 regs. LDS per k: 2x LDS.128, conflict-free (lanes with
//     equal q broadcast, distinct q hit distinct banks). X row loads are
//     4-lane duplicated but merge in the L1 coalescer; DRAM reads X once.
// ---------------------------------------------------------------------------
__global__ void k_gemm_norm(const float* __restrict__ X,
                            const float* __restrict__ W,
                            int n) {
    __shared__ float sW[IN_DIM * HID_DIM];   // 8 KB
    for (int i = threadIdx.x; i < IN_DIM * HID_DIM; i += blockDim.x)
        sW[i] = W[i];
    __syncthreads();

    int t = blockIdx.x * blockDim.x + threadIdx.x;
    int r = t >> 2;                  // row
    int q = t & 3;                   // column quarter
    if (r >= n) return;
    int c0 = q * 8;                  // first owned column

    float acc[8];
#pragma unroll
    for (int j = 0; j < 8; j++) acc[j] = 0.f;

    const float4* xr = reinterpret_cast<const float4*>(X + (size_t)r * IN_DIM);
#pragma unroll
    for (int k4 = 0; k4 < IN_DIM / 4; k4++) {
        float4 x = __ldg(xr + k4);
        int k = k4 * 4;
#pragma unroll
        for (int j = 0; j < 8; j++) {
            acc[j] = fmaf(x.x, sW[(k + 0) * HID_DIM + c0 + j],
                     fmaf(x.y, sW[(k + 1) * HID_DIM + c0 + j],
                     fmaf(x.z, sW[(k + 2) * HID_DIM + c0 + j],
                     fmaf(x.w, sW[(k + 3) * HID_DIM + c0 + j], acc[j]))));
        }
    }

    float nrm = rsqrtf(fmaxf((float)__ldg(&g_deg_out[r]), 1.0f));
    float4* hr = reinterpret_cast<float4*>(g_h + (size_t)r * HID_DIM + c0);
#pragma unroll
    for (int j4 = 0; j4 < 2; j4++) {
        float4 v;
        v.x = acc[j4 * 4 + 0] * nrm;
        v.y = acc[j4 * 4 + 1] * nrm;
        v.z = acc[j4 * 4 + 2] * nrm;
        v.w = acc[j4 * 4 + 3] * nrm;
        hr[j4] = v;
    }
}

// ---------------------------------------------------------------------------
// K3: scatter  out[dst] += h[src]  (+ in-degree count, lane p==0 per edge).
//     8 threads / edge, one float4 each: coalesced 128B gather,
//     vector red.global.add.v4.f32. Sits at the per-SM REDG lane floor
//     (12.8M + 1.6M red lanes ~= 50us); irreducible in fp32.
// ---------------------------------------------------------------------------
__global__ void k_scatter(const int* __restrict__ src,
                          const int* __restrict__ dst,
                          float* __restrict__ out,
                          int E) {
    long long tid = (long long)blockIdx.x * blockDim.x + threadIdx.x;
    int e = (int)(tid >> 3);
    if (e >= E) return;
    int p = (int)(tid & 7);

    int s = __ldg(src + e);
    int d = __ldg(dst + e);

    float4 v = __ldg(reinterpret_cast<const float4*>(g_h + (size_t)s * HID_DIM) + p);
    float* addr = out + (size_t)d * HID_DIM + p * 4;

    asm volatile("red.global.add.v4.f32 [%0], {%1, %2, %3, %4};"
                 :: "l"(addr), "f"(v.x), "f"(v.y), "f"(v.z), "f"(v.w)
                 : "memory");

    if (p == 0)
        atomicAdd(&g_deg_in[d], 1);      // consumed by k_finalize (after sync)
}

// ---------------------------------------------------------------------------
// K4: out = relu(out * rsqrt(max(deg_in,1)) + b)   (in place, vectorized)
//     Also re-zeros both degree arrays for the next kernel_launch call.
// ---------------------------------------------------------------------------
__global__ void k_finalize(float4* __restrict__ out4,
                           const float* __restrict__ b,
                           int n) {
    __shared__ float4 sb[HID_DIM / 4];
    if (threadIdx.x < HID_DIM / 4)
        sb[threadIdx.x] = reinterpret_cast<const float4*>(b)[threadIdx.x];
    __syncthreads();

    int tot4 = n * (HID_DIM / 4);
    int i = blockIdx.x * blockDim.x + threadIdx.x;
    if (i >= tot4) return;

    int row = i >> 3;
    int j4  = i & 7;
    float nrm = rsqrtf(fmaxf((float)g_deg_in[row], 1.0f));
    float4 v  = out4[i];
    float4 bb = sb[j4];
    v.x = fmaxf(v.x * nrm + bb.x, 0.f);
    v.y = fmaxf(v.y * nrm + bb.y, 0.f);
    v.z = fmaxf(v.z * nrm + bb.z, 0.f);
    v.w = fmaxf(v.w * nrm + bb.w, 0.f);
    out4[i] = v;

    // Reset counters for the next launch (one thread per row: j4 == 0)
    if (j4 == 0) {
        g_deg_in[row]  = 0;
        g_deg_out[row] = 0;
    }
}

// ---------------------------------------------------------------------------
extern "C" void kernel_launch(void* const* d_in, const int* in_sizes, int n_in,
                              void* d_out, int out_size) {
    const float* features = (const float*)d_in[0];
    const int*   src      = (const int*)  d_in[1];
    const int*   dst      = (const int*)  d_in[2];
    const float* W        = (const float*)d_in[3];
    const float* b        = (const float*)d_in[4];
    float*       out      = (float*)d_out;

    int n = in_sizes[0] / IN_DIM;   // 100000
    int E = in_sizes[1];            // 1600000

    const int B = 256;

    // K1: zero out + out-degree histogram (grid-stride over both)
    k_zero_hist<<<1184, B>>>((float4*)out, src, n, E);   // 148 SMs x 8 CTAs

    // K2: gemm + src-norm (4 threads per row -> 1563 blocks, high occupancy)
    long long t2 = (long long)n * 4;
    k_gemm_norm<<<(int)((t2 + B - 1) / B), B>>>(features, W, n);

    // K3: scatter (8 threads per edge) + in-degree count
    long long threads3 = (long long)E * 8;
    k_scatter<<<(int)((threads3 + B - 1) / B), B>>>(src, dst, out, E);

    // K4: finalize + counter reset
    int tot4 = n * (HID_DIM / 4);
    k_finalize<<<(tot4 + B - 1) / B, B>>>((float4*)out, b, n);
}

// round 17
// speedup vs baseline: 1.5748x; 1.5748x over previous
#include <cuda_runtime.h>
#include <cuda_bf16.h>
#include <cstdint>

// Problem constants (shapes fixed by the dataset; sizes re-derived from in_sizes)
#define MAX_NODES 100000
#define IN_DIM    64
#define HID_DIM   32

// Scratch (allocation-free rule: __device__ globals).
// Device globals are zero-initialized at module load, and k_finalize re-zeros
// both degree arrays after consuming them, so every kernel_launch call
// (correctness run, graph capture, every replay) starts from zeroed counters.
__device__ int   g_deg_out[MAX_NODES];
__device__ int   g_deg_in [MAX_NODES];
__device__ float g_h      [MAX_NODES * HID_DIM];   // (X@W) * norm_src

// ---------------------------------------------------------------------------
// K1: out-degree histogram (4 edges/unit via int4 loads -> 4 independent
//     REDGs in flight). Out-zeroing moved to a graph memset node.
// ---------------------------------------------------------------------------
__global__ void k_hist_out(const int* __restrict__ src, int E) {
    int tid = blockIdx.x * blockDim.x + threadIdx.x;
    int gstride = gridDim.x * blockDim.x;
    int units = (E + 3) / 4;
    for (int u = tid; u < units; u += gstride) {
        int base = u * 4;
        if (base + 3 < E) {
            int4 s = __ldg(reinterpret_cast<const int4*>(src + base));
            atomicAdd(&g_deg_out[s.x], 1);
            atomicAdd(&g_deg_out[s.y], 1);
            atomicAdd(&g_deg_out[s.z], 1);
            atomicAdd(&g_deg_out[s.w], 1);
        } else {
            for (int i = base; i < E; i++)
                atomicAdd(&g_deg_out[__ldg(src + i)], 1);
        }
    }
}

// ---------------------------------------------------------------------------
// K2: h = (X @ W) * rsqrt(max(deg_out,1))
//     One row per thread; W staged in smem (all-thread broadcast reads).
//     (Proven R13 shape — restructuring attempts in R15/R16 both regressed.)
// ---------------------------------------------------------------------------
__global__ void k_gemm_norm(const float* __restrict__ X,
                            const float* __restrict__ W,
                            int n) {
    __shared__ float sW[IN_DIM * HID_DIM];   // 8 KB
    for (int i = threadIdx.x; i < IN_DIM * HID_DIM; i += blockDim.x)
        sW[i] = W[i];
    __syncthreads();

    int r = blockIdx.x * blockDim.x + threadIdx.x;
    if (r >= n) return;

    float acc[HID_DIM];
#pragma unroll
    for (int j = 0; j < HID_DIM; j++) acc[j] = 0.f;

    const float4* xr = reinterpret_cast<const float4*>(X + (size_t)r * IN_DIM);
#pragma unroll 4
    for (int k4 = 0; k4 < IN_DIM / 4; k4++) {
        float4 x = __ldg(xr + k4);
        int k = k4 * 4;
#pragma unroll
        for (int j = 0; j < HID_DIM; j++) {
            acc[j] = fmaf(x.x, sW[(k + 0) * HID_DIM + j],
                     fmaf(x.y, sW[(k + 1) * HID_DIM + j],
                     fmaf(x.z, sW[(k + 2) * HID_DIM + j],
                     fmaf(x.w, sW[(k + 3) * HID_DIM + j], acc[j]))));
        }
    }

    float nrm = rsqrtf(fmaxf((float)g_deg_out[r], 1.0f));
    float4* hr = reinterpret_cast<float4*>(g_h + (size_t)r * HID_DIM);
#pragma unroll
    for (int j4 = 0; j4 < HID_DIM / 4; j4++) {
        float4 v;
        v.x = acc[j4 * 4 + 0] * nrm;
        v.y = acc[j4 * 4 + 1] * nrm;
        v.z = acc[j4 * 4 + 2] * nrm;
        v.w = acc[j4 * 4 + 3] * nrm;
        hr[j4] = v;
    }
}

// ---------------------------------------------------------------------------
// K3: scatter  out[dst] += h[src]  (+ in-degree count, lane p==0 per edge).
//     8 threads / edge, one float4 each: coalesced 128B gather,
//     vector red.global.add.v4.f32. Sits at the per-SM REDG lane floor
//     (~50us for 12.8M + 1.6M red lanes); irreducible in fp32.
// ---------------------------------------------------------------------------
__global__ void k_scatter(const int* __restrict__ src,
                          const int* __restrict__ dst,
                          float* __restrict__ out,
                          int E) {
    long long tid = (long long)blockIdx.x * blockDim.x + threadIdx.x;
    int e = (int)(tid >> 3);
    if (e >= E) return;
    int p = (int)(tid & 7);

    int s = __ldg(src + e);
    int d = __ldg(dst + e);

    float4 v = __ldg(reinterpret_cast<const float4*>(g_h + (size_t)s * HID_DIM) + p);
    float* addr = out + (size_t)d * HID_DIM + p * 4;

    asm volatile("red.global.add.v4.f32 [%0], {%1, %2, %3, %4};"
                 :: "l"(addr), "f"(v.x), "f"(v.y), "f"(v.z), "f"(v.w)
                 : "memory");

    if (p == 0)
        atomicAdd(&g_deg_in[d], 1);      // consumed by k_finalize (after sync)
}

// ---------------------------------------------------------------------------
// K4: out = relu(out * rsqrt(max(deg_in,1)) + b)   (in place, vectorized)
//     Also re-zeros both degree arrays for the next kernel_launch call.
// ---------------------------------------------------------------------------
__global__ void k_finalize(float4* __restrict__ out4,
                           const float* __restrict__ b,
                           int n) {
    __shared__ float4 sb[HID_DIM / 4];
    if (threadIdx.x < HID_DIM / 4)
        sb[threadIdx.x] = reinterpret_cast<const float4*>(b)[threadIdx.x];
    __syncthreads();

    int tot4 = n * (HID_DIM / 4);
    int i = blockIdx.x * blockDim.x + threadIdx.x;
    if (i >= tot4) return;

    int row = i >> 3;
    int j4  = i & 7;
    float nrm = rsqrtf(fmaxf((float)g_deg_in[row], 1.0f));
    float4 v  = out4[i];
    float4 bb = sb[j4];
    v.x = fmaxf(v.x * nrm + bb.x, 0.f);
    v.y = fmaxf(v.y * nrm + bb.y, 0.f);
    v.z = fmaxf(v.z * nrm + bb.z, 0.f);
    v.w = fmaxf(v.w * nrm + bb.w, 0.f);
    out4[i] = v;

    // Reset counters for the next launch (one thread per row: j4 == 0)
    if (j4 == 0) {
        g_deg_in[row]  = 0;
        g_deg_out[row] = 0;
    }
}

// ---------------------------------------------------------------------------
extern "C" void kernel_launch(void* const* d_in, const int* in_sizes, int n_in,
                              void* d_out, int out_size) {
    const float* features = (const float*)d_in[0];
    const int*   src      = (const int*)  d_in[1];
    const int*   dst      = (const int*)  d_in[2];
    const float* W        = (const float*)d_in[3];
    const float* b        = (const float*)d_in[4];
    float*       out      = (float*)d_out;

    int n = in_sizes[0] / IN_DIM;   // 100000
    int E = in_sizes[1];            // 1600000

    const int B = 256;

    // Zero the output accumulator via a graph memset node (DMA-rate fill,
    // no SM time). Graph-capturable; no allocation.
    cudaMemsetAsync(out, 0, (size_t)n * HID_DIM * sizeof(float), 0);

    // K1: out-degree histogram
    k_hist_out<<<1184, B>>>(src, E);                 // 148 SMs x 8 CTAs

    // K2: gemm + src-norm (one row per thread — proven fastest shape)
    k_gemm_norm<<<(n + B - 1) / B, B>>>(features, W, n);

    // K3: scatter (8 threads per edge) + in-degree count
    long long threads3 = (long long)E * 8;
    k_scatter<<<(int)((threads3 + B - 1) / B), B>>>(src, dst, out, E);

    // K4: finalize + counter reset
    int tot4 = n * (HID_DIM / 4);
    k_finalize<<<(tot4 + B - 1) / B, B>>>((float4*)out, b, n);
}